// round 1
// baseline (speedup 1.0000x reference)
#include <cuda_runtime.h>

// GCN fused layer:
//   support = y @ W                      (GEMM1, M=8192, N=1024, K=1024)
//   out     = relu(adj @ support / adj_sumrow + b + x)   (GEMM2 batched, 8x [1024x1024x1024])
//
// Inputs (metadata order): x[8,1024,1024] f32, y[8,1024,1024] f32,
//   adj[8,1024,1024] f32, adj_sumrow[8,1024,1] f32, W[1024,1024] f32, b[1024] f32
// Output: [8,1024,1024] f32

#define BM 128
#define BN 128
#define BK 8
#define TM 8
#define TN 8

// Scratch for the intermediate 'support' tensor (8*1024*1024 f32 = 32 MB).
__device__ float g_support[8u * 1024u * 1024u];

__global__ __launch_bounds__(256, 2) void gcn_sgemm_kernel(
    const float* __restrict__ A,   // [M, K] (per batch via strideA)
    const float* __restrict__ B,   // [K, N] (per batch via strideB)
    float* __restrict__ C,         // [M, N] (per batch via strideC)
    int M, int Ncols, int K,
    long strideA, long strideB, long strideC,
    const float* __restrict__ sumrow,  // [batches, M] (epilogue only)
    const float* __restrict__ bias,    // [Ncols]      (epilogue only)
    const float* __restrict__ xres,    // [batches, M, Ncols] residual (epilogue only)
    int do_epi)
{
    __shared__ float As[BK][BM];
    __shared__ float Bs[BK][BN];

    const int bx = blockIdx.x;
    const int by = blockIdx.y;
    const int bz = blockIdx.z;

    A += (long)bz * strideA + (long)by * BM * K;
    B += (long)bz * strideB;
    C += (long)bz * strideC;

    const int tid = threadIdx.x;
    const int tr = tid / 16;  // 0..15 -> thread row group
    const int tc = tid % 16;  // 0..15 -> thread col group

    // A tile loads: 128 rows x 8 cols; one float4 along K per thread
    const int aRow = tid / 2;            // 0..127
    const int aCol = (tid % 2) * 4;      // 0 or 4
    // B tile loads: 8 rows x 128 cols; one float4 along N per thread
    const int bRow = tid / 32;           // 0..7
    const int bCol = (tid % 32) * 4;     // 0..124

    float acc[TM][TN];
    #pragma unroll
    for (int i = 0; i < TM; i++)
        #pragma unroll
        for (int j = 0; j < TN; j++)
            acc[i][j] = 0.0f;

    const float* Aload = A + (long)aRow * K + aCol;
    const float* Bload = B + (long)bRow * Ncols + (long)bx * BN + bCol;

    for (int k0 = 0; k0 < K; k0 += BK) {
        // Stage A tile (transposed: As[k][m]) and B tile (Bs[k][n])
        float4 a4 = *reinterpret_cast<const float4*>(Aload + k0);
        As[aCol + 0][aRow] = a4.x;
        As[aCol + 1][aRow] = a4.y;
        As[aCol + 2][aRow] = a4.z;
        As[aCol + 3][aRow] = a4.w;

        float4 b4 = *reinterpret_cast<const float4*>(Bload + (long)k0 * Ncols);
        *reinterpret_cast<float4*>(&Bs[bRow][bCol]) = b4;

        __syncthreads();

        #pragma unroll
        for (int k = 0; k < BK; k++) {
            float ra[TM], rb[TN];
            #pragma unroll
            for (int i = 0; i < TM; i += 4) {
                float4 v = *reinterpret_cast<const float4*>(&As[k][tr * TM + i]);
                ra[i + 0] = v.x; ra[i + 1] = v.y; ra[i + 2] = v.z; ra[i + 3] = v.w;
            }
            #pragma unroll
            for (int j = 0; j < TN; j += 4) {
                float4 v = *reinterpret_cast<const float4*>(&Bs[k][tc * TN + j]);
                rb[j + 0] = v.x; rb[j + 1] = v.y; rb[j + 2] = v.z; rb[j + 3] = v.w;
            }
            #pragma unroll
            for (int i = 0; i < TM; i++)
                #pragma unroll
                for (int j = 0; j < TN; j++)
                    acc[i][j] = fmaf(ra[i], rb[j], acc[i][j]);
        }
        __syncthreads();
    }

    const int row0 = by * BM + tr * TM;
    const int col0 = bx * BN + tc * TN;

    if (do_epi) {
        const long xbase = (long)bz * M * Ncols;
        #pragma unroll
        for (int i = 0; i < TM; i++) {
            const int row = row0 + i;
            const float inv = 1.0f / sumrow[(long)bz * M + row];
            const long rbase = xbase + (long)row * Ncols;
            #pragma unroll
            for (int j = 0; j < TN; j += 4) {
                const int col = col0 + j;
                float4 xv = *reinterpret_cast<const float4*>(&xres[rbase + col]);
                float4 bv = *reinterpret_cast<const float4*>(&bias[col]);
                float4 o;
                o.x = fmaxf(acc[i][j + 0] * inv + bv.x + xv.x, 0.0f);
                o.y = fmaxf(acc[i][j + 1] * inv + bv.y + xv.y, 0.0f);
                o.z = fmaxf(acc[i][j + 2] * inv + bv.z + xv.z, 0.0f);
                o.w = fmaxf(acc[i][j + 3] * inv + bv.w + xv.w, 0.0f);
                *reinterpret_cast<float4*>(&C[(long)row * Ncols + col]) = o;
            }
        }
    } else {
        #pragma unroll
        for (int i = 0; i < TM; i++) {
            const int row = row0 + i;
            #pragma unroll
            for (int j = 0; j < TN; j += 4) {
                float4 o;
                o.x = acc[i][j + 0];
                o.y = acc[i][j + 1];
                o.z = acc[i][j + 2];
                o.w = acc[i][j + 3];
                *reinterpret_cast<float4*>(&C[(long)row * Ncols + (col0 + j)]) = o;
            }
        }
    }
}

extern "C" void kernel_launch(void* const* d_in, const int* in_sizes, int n_in,
                              void* d_out, int out_size) {
    const float* x      = (const float*)d_in[0];
    const float* y      = (const float*)d_in[1];
    const float* adj    = (const float*)d_in[2];
    const float* sumrow = (const float*)d_in[3];
    const float* W      = (const float*)d_in[4];
    const float* bias   = (const float*)d_in[5];
    float* out = (float*)d_out;

    float* support = nullptr;
    cudaGetSymbolAddress((void**)&support, g_support);

    dim3 block(256);

    // GEMM1: support[8192,1024] = y[8192,1024] @ W[1024,1024]
    {
        dim3 grid(1024 / BN, 8192 / BM, 1);
        gcn_sgemm_kernel<<<grid, block>>>(
            y, W, support,
            8192, 1024, 1024,
            0, 0, 0,
            nullptr, nullptr, nullptr, 0);
    }

    // GEMM2 (batched, fused epilogue):
    //   out_b = relu(adj_b @ support_b / sumrow_b + bias + x_b)
    {
        dim3 grid(1024 / BN, 1024 / BM, 8);
        const long bstride = 1024L * 1024L;
        gcn_sgemm_kernel<<<grid, block>>>(
            adj, support, out,
            1024, 1024, 1024,
            bstride, bstride, bstride,
            sumrow, bias, x, 1);
    }
}